// round 17
// baseline (speedup 1.0000x reference)
#include <cuda_runtime.h>
#include <cuda_fp16.h>
#include <stdint.h>

#define SEQ 4096
#define E   2048
#define SE  (SEQ * E)
#define EE  (E * E)
#define SS  ((size_t)SEQ * SEQ)

// ---------------------------------------------------------------------------
// Scratch (__device__ globals per allocation-free rule)
// g_s: s logits (fp32) before softmax, then split-K partials for out-GEMM.
// ---------------------------------------------------------------------------
__device__ __half g_xh [SE];
__device__ __half g_Wqh[EE], g_Wkh[EE], g_Wvh[EE];
__device__ __half g_qh [SE], g_kh [SE], g_vTh[SE];
__device__ __half g_wh [SS];
__device__ float  g_s  [SS];

// ---------------------------------------------------------------------------
// PTX helpers
// ---------------------------------------------------------------------------
__device__ __forceinline__ uint32_t smem_u32(const void* p) {
    uint32_t a;
    asm("{ .reg .u64 t; cvta.to.shared.u64 t, %1; cvt.u32.u64 %0, t; }" : "=r"(a) : "l"(p));
    return a;
}
#define CP_ASYNC_16(dst, src) \
    asm volatile("cp.async.cg.shared.global [%0], [%1], 16;" :: "r"(dst), "l"(src))
#define CP_ASYNC_COMMIT() asm volatile("cp.async.commit_group;" ::: "memory")
#define CP_ASYNC_WAIT(n)  asm volatile("cp.async.wait_group %0;" :: "n"(n) : "memory")
#define LDSM4(r, a) \
    asm volatile("ldmatrix.sync.aligned.m8n8.x4.shared.b16 {%0,%1,%2,%3}, [%4];" \
        : "=r"((r)[0]), "=r"((r)[1]), "=r"((r)[2]), "=r"((r)[3]) : "r"(a))
#define MMAH(d, a, b0, b1) \
    asm volatile("mma.sync.aligned.m16n8k16.row.col.f32.f16.f16.f32 " \
        "{%0,%1,%2,%3}, {%4,%5,%6,%7}, {%8,%9}, {%0,%1,%2,%3};" \
        : "+f"((d)[0]), "+f"((d)[1]), "+f"((d)[2]), "+f"((d)[3]) \
        : "r"((a)[0]), "r"((a)[1]), "r"((a)[2]), "r"((a)[3]), "r"(b0), "r"(b1))
__device__ __forceinline__ uint32_t sw128(uint32_t o) { return o ^ ((o >> 3) & 0x70); }

// ===========================================================================
// CORE1 (fp16, 1-pass, BK=64): C = A * B^T
// 128x128 tile, 128B rows (SW128), 2 tiles/stage (32KB), 5 stages (160KB),
// warp tile 64x32, 4 k16 MMA groups per barrier (64 MMAs/warp/iteration),
// fragment double-buffering, proven 5-stage pipeline protocol.
// Epilogue: fp32 Cf if non-null, else fp16 Ch.
// ===========================================================================
#define BK       64
#define TILE_B   16384                // 128 rows x 128B
#define STAGE1   (2 * TILE_B)         // 32768
#define SMEM1    (5 * STAGE1)         // 163840

struct Ld1 { const __half *pA, *pB; uint32_t d0, d1, d2, d3; int he; };

__device__ __forceinline__ void load_stage1(uint32_t sb, int st, const Ld1& L, int k0)
{
    uint32_t s = sb + st * STAGE1;
    const __half* a = L.pA + k0 + L.he;
    const __half* b = L.pB + k0 + L.he;
    CP_ASYNC_16(s + L.d0, a);           CP_ASYNC_16(s + L.d1, a + 8);
    CP_ASYNC_16(s + L.d2, a + 16);      CP_ASYNC_16(s + L.d3, a + 24);
    CP_ASYNC_16(s + TILE_B + L.d0, b);  CP_ASYNC_16(s + TILE_B + L.d1, b + 8);
    CP_ASYNC_16(s + TILE_B + L.d2, b + 16); CP_ASYNC_16(s + TILE_B + L.d3, b + 24);
    CP_ASYNC_COMMIT();
}

struct Fr1 { uint32_t ah[4][4], bh[2][4]; };

__device__ __forceinline__ void load_frags1(Fr1& f, uint32_t stb,
                                            uint32_t ab, uint32_t bb, int k16)
{
    #pragma unroll
    for (int mi = 0; mi < 4; ++mi) {
        const uint32_t off = ab + (uint32_t)mi * 2048 + k16 * 32;
        LDSM4(f.ah[mi], stb + sw128(off));
    }
    #pragma unroll
    for (int ng = 0; ng < 2; ++ng) {
        const uint32_t off = bb + (uint32_t)ng * 2048 + k16 * 32;
        LDSM4(f.bh[ng], stb + TILE_B + sw128(off));
    }
}

__device__ __forceinline__ void mma_group1(float acc[4][4][4], const Fr1& f)
{
    #pragma unroll
    for (int mi = 0; mi < 4; ++mi)
        #pragma unroll
        for (int ni = 0; ni < 4; ++ni) {
            const int ng = ni >> 1, sel = (ni & 1) * 2;
            MMAH(acc[mi][ni], f.ah[mi], f.bh[ng][sel], f.bh[ng][sel + 1]);
        }
}

__device__ __forceinline__ void gemm_core1(
    const __half* __restrict__ A, const __half* __restrict__ B,
    float* __restrict__ Cf, __half* __restrict__ Ch,
    int N, int K, int Ks, int bm, int bn)
{
    extern __shared__ __align__(1024) char smem[];
    const uint32_t sb = smem_u32(smem);
    const int tid = threadIdx.x, lane = tid & 31, wid = tid >> 5;
    const int wm = (wid & 1) * 64, wn = (wid >> 1) * 32;

    Ld1 L;
    {
        const int lrow = tid >> 1, lhalf = (tid & 1) * 64;   // bytes in 128B row
        uint32_t o = (uint32_t)lrow * 128 + lhalf;
        L.d0 = sw128(o);      L.d1 = sw128(o + 16);
        L.d2 = sw128(o + 32); L.d3 = sw128(o + 48);
        L.he = lhalf >> 1;
        L.pA = A + (size_t)(bm + lrow) * Ks;
        L.pB = B + (size_t)(bn + lrow) * Ks;
    }
    const uint32_t ab = (uint32_t)(wm + (lane & 15)) * 128 + (lane >> 4) * 16;
    const uint32_t bb = (uint32_t)(wn + (lane & 7) + ((lane >> 4) << 3)) * 128
                      + ((lane >> 3) & 1) * 16;

    float acc[4][4][4];
    #pragma unroll
    for (int i = 0; i < 4; ++i)
        #pragma unroll
        for (int j = 0; j < 4; ++j)
            #pragma unroll
            for (int r = 0; r < 4; ++r) acc[i][j][r] = 0.0f;

    const int nk = K / BK;
    #pragma unroll
    for (int s = 0; s < 4; ++s) load_stage1(sb, s, L, s * BK);
    CP_ASYNC_WAIT(3);
    __syncthreads();

    Fr1 fa, fb;
    load_frags1(fa, sb, ab, bb, 0);

    int st = 0, stw = 4;
    for (int i = 0; i < nk; ++i) {
        const uint32_t stb = sb + st * STAGE1;

        // 4 k16 groups per stage, double-buffered fragments
        load_frags1(fb, stb, ab, bb, 1);
        mma_group1(acc, fa);
        load_frags1(fa, stb, ab, bb, 2);
        mma_group1(acc, fb);
        load_frags1(fb, stb, ab, bb, 3);
        mma_group1(acc, fa);

        if (i + 4 < nk) load_stage1(sb, stw, L, (i + 4) * BK);
        else            CP_ASYNC_COMMIT();
        CP_ASYNC_WAIT(3);
        __syncthreads();

        if (++st  == 5) st  = 0;
        if (++stw == 5) stw = 0;
        if (i + 1 < nk) load_frags1(fa, sb + st * STAGE1, ab, bb, 0);
        mma_group1(acc, fb);
    }

    const int er = lane >> 2, ec = (lane & 3) * 2;
    #pragma unroll
    for (int mi = 0; mi < 4; ++mi)
        #pragma unroll
        for (int ni = 0; ni < 4; ++ni) {
            const int r0 = bm + wm + mi * 16 + er;
            const int c0 = bn + wn + ni * 8 + ec;
            float* a = acc[mi][ni];
            if (Cf) {
                *(float2*)(Cf + (size_t)r0 * N + c0)       = make_float2(a[0], a[1]);
                *(float2*)(Cf + (size_t)(r0 + 8) * N + c0) = make_float2(a[2], a[3]);
            } else {
                #pragma unroll
                for (int h = 0; h < 2; ++h) {
                    size_t off = (size_t)(r0 + 8 * h) * N + c0;
                    *(__half2*)(Ch + off) =
                        __halves2half2(__float2half(a[2 * h]), __float2half(a[2 * h + 1]));
                }
            }
        }
}

// ===========================================================================
// Driver kernels
// ===========================================================================
// Merged QKV (1536 CTAs): q = xh Wqh^T, k = xh Wkh^T, vT = Wvh xh^T
__global__ __launch_bounds__(256, 1)
void qkv_gemm(const __half* __restrict__ xh,
              const __half* __restrict__ Wqh, const __half* __restrict__ Wkh,
              const __half* __restrict__ Wvh,
              __half* __restrict__ qh, __half* __restrict__ kh, __half* __restrict__ vTh)
{
    const int idx = blockIdx.x;
    if (idx < 1024) {
        const int j = idx & 511;
        const int bn = (j & 15) * 128, bm = (j >> 4) * 128;
        if (idx < 512)
            gemm_core1(xh, Wqh, nullptr, qh, E, E, E, bm, bn);
        else
            gemm_core1(xh, Wkh, nullptr, kh, E, E, E, bm, bn);
    } else {
        const int j = idx - 1024;
        const int bn = (j & 31) * 128, bm = (j >> 5) * 128;
        gemm_core1(Wvh, xh, nullptr, vTh, SEQ, E, E, bm, bn);
    }
}

// s = qh @ kh^T -> fp32
__global__ __launch_bounds__(256, 1)
void s_gemm(const __half* __restrict__ qh, const __half* __restrict__ kh,
            float* __restrict__ s)
{
    gemm_core1(qh, kh, s, nullptr, SEQ, E, E, blockIdx.y * 128, blockIdx.x * 128);
}

// out = wh @ vTh^T, split-K (1024 CTAs): disjoint fp32 partials
__global__ __launch_bounds__(256, 1)
void out_gemm_sk(const __half* __restrict__ wh, const __half* __restrict__ vTh,
                 float* __restrict__ part)
{
    const int idx = blockIdx.x;
    const int h = idx >> 9;
    const int j = idx & 511;
    const int bn = (j & 15) * 128, bm = (j >> 4) * 128;
    const int koff = h * (SEQ / 2);
    gemm_core1(wh + koff, vTh + koff, part + (size_t)h * SE, nullptr,
               E, SEQ / 2, SEQ, bm, bn);
}

__global__ void reduce_add(const float* __restrict__ part, float* __restrict__ out, int n4)
{
    int i = blockIdx.x * blockDim.x + threadIdx.x;
    if (i >= n4) return;
    float4 a = ((const float4*)part)[i];
    float4 b = ((const float4*)part)[i + n4];
    ((float4*)out)[i] = make_float4(a.x + b.x, a.y + b.y, a.z + b.z, a.w + b.w);
}

// ===========================================================================
// Elementwise
// ===========================================================================
#define X4 (SE / 4)
#define W4 (EE / 4)

// fp32 -> fp16, all four inputs in one launch
__global__ void conv_all(const float* __restrict__ x,  const float* __restrict__ Wq,
                         const float* __restrict__ Wk, const float* __restrict__ Wv,
                         __half* __restrict__ xh, __half* __restrict__ Wqh,
                         __half* __restrict__ Wkh, __half* __restrict__ Wvh)
{
    int i = blockIdx.x * blockDim.x + threadIdx.x;
    const float* src; __half* hi; int off;
    if (i < X4)               { src = x;  hi = xh;  off = i; }
    else if (i < X4 + W4)     { src = Wq; hi = Wqh; off = i - X4; }
    else if (i < X4 + 2 * W4) { src = Wk; hi = Wkh; off = i - X4 - W4; }
    else if (i < X4 + 3 * W4) { src = Wv; hi = Wvh; off = i - X4 - 2 * W4; }
    else return;

    float4 v = ((const float4*)src)[off];
    ((__half2*)hi)[2 * off]     = __halves2half2(__float2half(v.x), __float2half(v.y));
    ((__half2*)hi)[2 * off + 1] = __halves2half2(__float2half(v.z), __float2half(v.w));
}

// ---------------------------------------------------------------------------
// Row softmax: fp32 in (float4), fp16 hi out, scale fused
// ---------------------------------------------------------------------------
__inline__ __device__ float warp_max(float v) {
    #pragma unroll
    for (int o = 16; o > 0; o >>= 1) v = fmaxf(v, __shfl_xor_sync(0xffffffffu, v, o));
    return v;
}
__inline__ __device__ float warp_sum(float v) {
    #pragma unroll
    for (int o = 16; o > 0; o >>= 1) v += __shfl_xor_sync(0xffffffffu, v, o);
    return v;
}

__global__ __launch_bounds__(256)
void softmax_rows(const float* __restrict__ S, __half* __restrict__ Wh)
{
    const int rowi = blockIdx.x;
    const float4* p4 = (const float4*)(S + (size_t)rowi * SEQ);
    const float scale = 0.022097086912079608f;  // 1/sqrt(2048)
    const int tid = threadIdx.x, lane = tid & 31, wid = tid >> 5;

    __shared__ float red[8];

    float4 v[4];
    float m = -1e30f;
    #pragma unroll
    for (int i = 0; i < 4; ++i) {
        float4 t = p4[tid + i * 256];
        v[i] = make_float4(t.x * scale, t.y * scale, t.z * scale, t.w * scale);
        m = fmaxf(m, fmaxf(fmaxf(v[i].x, v[i].y), fmaxf(v[i].z, v[i].w)));
    }
    m = warp_max(m);
    if (lane == 0) red[wid] = m;
    __syncthreads();
    if (wid == 0) {
        float t = (lane < 8) ? red[lane] : -1e30f;
        t = warp_max(t);
        if (lane == 0) red[0] = t;
    }
    __syncthreads();
    m = red[0];
    __syncthreads();

    float sum = 0.0f;
    #pragma unroll
    for (int i = 0; i < 4; ++i) {
        v[i].x = __expf(v[i].x - m);  v[i].y = __expf(v[i].y - m);
        v[i].z = __expf(v[i].z - m);  v[i].w = __expf(v[i].w - m);
        sum += (v[i].x + v[i].y) + (v[i].z + v[i].w);
    }
    sum = warp_sum(sum);
    if (lane == 0) red[wid] = sum;
    __syncthreads();
    if (wid == 0) {
        float t = (lane < 8) ? red[lane] : 0.0f;
        t = warp_sum(t);
        if (lane == 0) red[0] = t;
    }
    __syncthreads();
    const float inv = 1.0f / red[0];

    #pragma unroll
    for (int i = 0; i < 4; ++i) {
        const size_t base = (size_t)rowi * SEQ + (size_t)(tid + i * 256) * 4;
        __half h0 = __float2half(v[i].x * inv), h1 = __float2half(v[i].y * inv);
        __half h2 = __float2half(v[i].z * inv), h3 = __float2half(v[i].w * inv);
        *(__half2*)(Wh + base)     = __halves2half2(h0, h1);
        *(__half2*)(Wh + base + 2) = __halves2half2(h2, h3);
    }
}

// ===========================================================================
// kernel_launch
// ===========================================================================
extern "C" void kernel_launch(void* const* d_in, const int* in_sizes, int n_in,
                              void* d_out, int out_size)
{
    const float* x  = (const float*)d_in[0];
    const float* Wq = (const float*)d_in[1];
    const float* Wk = (const float*)d_in[2];
    const float* Wv = (const float*)d_in[3];
    float* out = (float*)d_out;

    cudaFuncSetAttribute(qkv_gemm,    cudaFuncAttributeMaxDynamicSharedMemorySize, SMEM1);
    cudaFuncSetAttribute(s_gemm,      cudaFuncAttributeMaxDynamicSharedMemorySize, SMEM1);
    cudaFuncSetAttribute(out_gemm_sk, cudaFuncAttributeMaxDynamicSharedMemorySize, SMEM1);

    __half *xh, *Wqh, *Wkh, *Wvh, *qh, *kh, *vTh, *wh;
    float* s;
    cudaGetSymbolAddress((void**)&xh,  g_xh);
    cudaGetSymbolAddress((void**)&Wqh, g_Wqh);
    cudaGetSymbolAddress((void**)&Wkh, g_Wkh);
    cudaGetSymbolAddress((void**)&Wvh, g_Wvh);
    cudaGetSymbolAddress((void**)&qh,  g_qh);
    cudaGetSymbolAddress((void**)&kh,  g_kh);
    cudaGetSymbolAddress((void**)&vTh, g_vTh);
    cudaGetSymbolAddress((void**)&wh,  g_wh);
    cudaGetSymbolAddress((void**)&s,   g_s);

    // 1. convert inputs to fp16
    const int total4 = X4 + 3 * W4;
    conv_all<<<(total4 + 255) / 256, 256>>>(x, Wq, Wk, Wv, xh, Wqh, Wkh, Wvh);

    // 2. q, k, vT in one launch (1-pass, BK=64)
    qkv_gemm<<<1536, 256, SMEM1>>>(xh, Wqh, Wkh, Wvh, qh, kh, vTh);

    // 3. s = q @ k^T -> fp32
    s_gemm<<<dim3(SEQ / 128, SEQ / 128), 256, SMEM1>>>(qh, kh, s);

    // 4. softmax -> w (fp16)
    softmax_rows<<<SEQ, 256>>>(s, wh);

    // 5. out = w @ vT^T, split-K -> partials in g_s (dead after softmax)
    out_gemm_sk<<<1024, 256, SMEM1>>>(wh, vTh, s);

    // 6. final reduce
    const int n4 = SE / 4;
    reduce_add<<<(n4 + 255) / 256, 256>>>(s, out, n4);
}